// round 6
// baseline (speedup 1.0000x reference)
#include <cuda_runtime.h>
#include <math.h>

// Mutual cross attention, B=8, L=2048, D=512, fp32.
// out = attn(x1, x2, x2) + attn(x2, x1, x1)   (flash-style, two passes)

#define B_   8
#define L_   2048
#define D_   512
#define BQ   32            // query rows per block
#define BK   32            // key rows per tile
#define PADF 4             // row padding in floats (row = 2064 B, shifts banks by 16B/row)
#define ROWF (D_ + PADF)   // 516 floats per smem row
#define NTH  256
#define NKT  (L_ / BK)     // 64 key tiles

// ---------- packed f32x2 FMA (Blackwell FFMA2) ----------
__device__ __forceinline__ float2 ffma2(float2 a, float2 b, float2 c) {
    float2 d;
    asm("{\n\t"
        ".reg .b64 ra, rb, rc, rd;\n\t"
        "mov.b64 ra, {%2, %3};\n\t"
        "mov.b64 rb, {%4, %5};\n\t"
        "mov.b64 rc, {%6, %7};\n\t"
        "fma.rn.f32x2 rd, ra, rb, rc;\n\t"
        "mov.b64 {%0, %1}, rd;\n\t"
        "}"
        : "=f"(d.x), "=f"(d.y)
        : "f"(a.x), "f"(a.y), "f"(b.x), "f"(b.y), "f"(c.x), "f"(c.y));
    return d;
}

// ---------- cp.async helpers ----------
__device__ __forceinline__ void cp_async16(float* smem_dst, const float* gmem_src) {
    unsigned saddr = (unsigned)__cvta_generic_to_shared(smem_dst);
    asm volatile("cp.async.cg.shared.global [%0], [%1], 16;" :: "r"(saddr), "l"(gmem_src));
}
__device__ __forceinline__ void cp_commit() { asm volatile("cp.async.commit_group;"); }
__device__ __forceinline__ void cp_wait0()  { asm volatile("cp.async.wait_group 0;"); }

template <bool ACCUM>
__global__ void __launch_bounds__(NTH, 1)
mca_attn_kernel(const float* __restrict__ Qg,   // [B, L, D] queries
                const float* __restrict__ KVg,  // [B, L, D] keys == values
                float* __restrict__ Og)         // [B, L, D]
{
    extern __shared__ float smem[];
    float* Qs  = smem;                 // BQ * ROWF
    float* KV0 = Qs  + BQ * ROWF;      // BK * ROWF
    float* KV1 = KV0 + BK * ROWF;      // BK * ROWF
    float* Ps  = KV1 + BK * ROWF;      // BQ * 33 (probabilities tile)

    const int tid = threadIdx.x;
    const int qt  = blockIdx.x;        // query tile 0..63
    const int b   = blockIdx.y;        // batch
    const int q   = tid >> 3;          // local query row 0..31
    const int s   = tid & 7;           // 8-way split: k-groups for S, d-slices for PV

    const float scale = 0.04419417382415922f;  // 1/sqrt(512)

    const float* qbase = Qg  + ((size_t)b * L_ + (size_t)qt * BQ) * D_;
    const float* kbase = KVg + (size_t)b * L_ * D_;

    // --- async load Q tile + KV tile 0 (32 rows x 128 float4 each; 16 per thread) ---
    #pragma unroll
    for (int i = 0; i < 16; ++i) {
        int f  = tid + i * NTH;        // float4 index 0..4095
        int r  = f >> 7;
        int c4 = f & 127;
        cp_async16(Qs + r * ROWF + c4 * 4, qbase + r * D_ + c4 * 4);
    }
    #pragma unroll
    for (int i = 0; i < 16; ++i) {
        int f  = tid + i * NTH;
        int r  = f >> 7;
        int c4 = f & 127;
        cp_async16(KV0 + r * ROWF + c4 * 4, kbase + r * D_ + c4 * 4);
    }
    cp_commit();

    // accumulator: this thread owns query row q, interleaved d-slices d4 = s + 8g
    float2 acc[32];
    #pragma unroll
    for (int j = 0; j < 32; ++j) acc[j] = make_float2(0.f, 0.f);
    float m = -INFINITY;
    float l = 0.f;

    cp_wait0();
    __syncthreads();

    for (int kt = 0; kt < NKT; ++kt) {
        float* cur = (kt & 1) ? KV1 : KV0;
        float* nxt = (kt & 1) ? KV0 : KV1;

        // prefetch next KV tile into the buffer we finished with last iteration
        if (kt + 1 < NKT) {
            const float* g = kbase + (size_t)(kt + 1) * BK * D_;
            #pragma unroll
            for (int i = 0; i < 16; ++i) {
                int f  = tid + i * NTH;
                int r  = f >> 7;
                int c4 = f & 127;
                cp_async16(nxt + r * ROWF + c4 * 4, g + r * D_ + c4 * 4);
            }
            cp_commit();
        }

        // ---- S = Q . K^T on this tile: thread computes S[q][s + 8c], c = 0..3 ----
        float2 sa0 = make_float2(0.f, 0.f), sa1 = sa0, sa2 = sa0, sa3 = sa0;
        const float4* qrow = reinterpret_cast<const float4*>(Qs + q * ROWF);
        const float4* k0   = reinterpret_cast<const float4*>(cur + (s +  0) * ROWF);
        const float4* k1   = reinterpret_cast<const float4*>(cur + (s +  8) * ROWF);
        const float4* k2   = reinterpret_cast<const float4*>(cur + (s + 16) * ROWF);
        const float4* k3   = reinterpret_cast<const float4*>(cur + (s + 24) * ROWF);
        #pragma unroll 4
        for (int dq = 0; dq < D_ / 4; ++dq) {
            float4 qv = qrow[dq];
            float2 ql = make_float2(qv.x, qv.y);
            float2 qh = make_float2(qv.z, qv.w);
            float4 kv;
            kv = k0[dq];
            sa0 = ffma2(ql, make_float2(kv.x, kv.y), sa0);
            sa0 = ffma2(qh, make_float2(kv.z, kv.w), sa0);
            kv = k1[dq];
            sa1 = ffma2(ql, make_float2(kv.x, kv.y), sa1);
            sa1 = ffma2(qh, make_float2(kv.z, kv.w), sa1);
            kv = k2[dq];
            sa2 = ffma2(ql, make_float2(kv.x, kv.y), sa2);
            sa2 = ffma2(qh, make_float2(kv.z, kv.w), sa2);
            kv = k3[dq];
            sa3 = ffma2(ql, make_float2(kv.x, kv.y), sa3);
            sa3 = ffma2(qh, make_float2(kv.z, kv.w), sa3);
        }
        float sv0 = (sa0.x + sa0.y) * scale;
        float sv1 = (sa1.x + sa1.y) * scale;
        float sv2 = (sa2.x + sa2.y) * scale;
        float sv3 = (sa3.x + sa3.y) * scale;

        // ---- online softmax over this tile's 32 keys (row group = 8 lanes) ----
        float mt = fmaxf(fmaxf(sv0, sv1), fmaxf(sv2, sv3));
        mt = fmaxf(mt, __shfl_xor_sync(0xffffffffu, mt, 1));
        mt = fmaxf(mt, __shfl_xor_sync(0xffffffffu, mt, 2));
        mt = fmaxf(mt, __shfl_xor_sync(0xffffffffu, mt, 4));
        float mnew = fmaxf(m, mt);
        float corr = __expf(m - mnew);           // exp(-inf)=0 on first tile
        float p0 = __expf(sv0 - mnew);
        float p1 = __expf(sv1 - mnew);
        float p2 = __expf(sv2 - mnew);
        float p3 = __expf(sv3 - mnew);
        float psum = p0 + p1 + p2 + p3;
        psum += __shfl_xor_sync(0xffffffffu, psum, 1);
        psum += __shfl_xor_sync(0xffffffffu, psum, 2);
        psum += __shfl_xor_sync(0xffffffffu, psum, 4);
        l = l * corr + psum;
        m = mnew;

        // share probabilities across the row group
        Ps[q * 33 + s +  0] = p0;
        Ps[q * 33 + s +  8] = p1;
        Ps[q * 33 + s + 16] = p2;
        Ps[q * 33 + s + 24] = p3;

        // rescale accumulator
        #pragma unroll
        for (int j = 0; j < 32; ++j) { acc[j].x *= corr; acc[j].y *= corr; }

        __syncthreads();   // Ps visible to whole block

        // ---- PV: acc[q, d-slice] += sum_k p[q][k] * V[k][d-slice] ----
        #pragma unroll 4
        for (int k = 0; k < BK; ++k) {
            float pv = Ps[q * 33 + k];
            float2 p2v = make_float2(pv, pv);
            const float4* vrow = reinterpret_cast<const float4*>(cur + k * ROWF) + s;
            #pragma unroll
            for (int g = 0; g < 16; ++g) {
                float4 v4 = vrow[8 * g];          // interleaved slices: conflict-free
                acc[2 * g]     = ffma2(p2v, make_float2(v4.x, v4.y), acc[2 * g]);
                acc[2 * g + 1] = ffma2(p2v, make_float2(v4.z, v4.w), acc[2 * g + 1]);
            }
        }

        cp_wait0();        // next tile's data landed (had a whole compute phase)
        __syncthreads();   // all reads of cur/Ps done before next prefetch/overwrite
    }

    // ---- epilogue: out = acc / l  (+ previous pass if ACCUM) ----
    float invl = 1.0f / l;
    float* orow = Og + ((size_t)b * L_ + (size_t)qt * BQ + q) * D_;
    #pragma unroll
    for (int g = 0; g < 16; ++g) {
        int d4 = s + 8 * g;                       // interleaved float4 slice
        float4 o;
        o.x = acc[2 * g].x     * invl;
        o.y = acc[2 * g].y     * invl;
        o.z = acc[2 * g + 1].x * invl;
        o.w = acc[2 * g + 1].y * invl;
        float4* optr = reinterpret_cast<float4*>(orow + d4 * 4);
        if (ACCUM) {
            float4 prev = *optr;
            o.x += prev.x; o.y += prev.y; o.z += prev.z; o.w += prev.w;
        }
        *optr = o;
    }
}

extern "C" void kernel_launch(void* const* d_in, const int* in_sizes, int n_in,
                              void* d_out, int out_size)
{
    (void)in_sizes; (void)n_in; (void)out_size;
    const float* x1 = (const float*)d_in[0];
    const float* x2 = (const float*)d_in[1];
    float* out = (float*)d_out;

    const size_t SMEM = (size_t)(BQ * ROWF + 2 * BK * ROWF + BQ * 33) * sizeof(float); // 202368 B
    cudaFuncSetAttribute(mca_attn_kernel<false>, cudaFuncAttributeMaxDynamicSharedMemorySize, (int)SMEM);
    cudaFuncSetAttribute(mca_attn_kernel<true>,  cudaFuncAttributeMaxDynamicSharedMemorySize, (int)SMEM);

    dim3 grid(L_ / BQ, B_);
    // pass 1: out  = softmax_k(x1 x2^T / sqrt(d)) x2
    mca_attn_kernel<false><<<grid, NTH, SMEM>>>(x1, x2, out);
    // pass 2: out += softmax_q(x2 x1^T / sqrt(d)) x1   (transpose-softmax branch)
    mca_attn_kernel<true ><<<grid, NTH, SMEM>>>(x2, x1, out);
}

// round 7
// speedup vs baseline: 1.0009x; 1.0009x over previous
#include <cuda_runtime.h>
#include <math.h>

// Mutual cross attention, B=8, L=2048, D=512, fp32.
// out = attn(x1, x2, x2) + attn(x2, x1, x1)   (flash-style, two passes)

#define B_   8
#define L_   2048
#define D_   512
#define BQ   32            // query rows per block
#define BK   32            // key rows per tile
#define PADF 4             // row padding in floats (row = 2064 B, shifts banks by 16B/row)
#define ROWF (D_ + PADF)   // 516 floats per smem row
#define NTH  256
#define NKT  (L_ / BK)     // 64 key tiles

// ---------- packed f32x2 FMA (Blackwell FFMA2) ----------
__device__ __forceinline__ float2 ffma2(float2 a, float2 b, float2 c) {
    float2 d;
    asm("{\n\t"
        ".reg .b64 ra, rb, rc, rd;\n\t"
        "mov.b64 ra, {%2, %3};\n\t"
        "mov.b64 rb, {%4, %5};\n\t"
        "mov.b64 rc, {%6, %7};\n\t"
        "fma.rn.f32x2 rd, ra, rb, rc;\n\t"
        "mov.b64 {%0, %1}, rd;\n\t"
        "}"
        : "=f"(d.x), "=f"(d.y)
        : "f"(a.x), "f"(a.y), "f"(b.x), "f"(b.y), "f"(c.x), "f"(c.y));
    return d;
}

// ---------- cp.async helpers ----------
__device__ __forceinline__ void cp_async16(float* smem_dst, const float* gmem_src) {
    unsigned saddr = (unsigned)__cvta_generic_to_shared(smem_dst);
    asm volatile("cp.async.cg.shared.global [%0], [%1], 16;" :: "r"(saddr), "l"(gmem_src));
}
__device__ __forceinline__ void cp_commit() { asm volatile("cp.async.commit_group;"); }
__device__ __forceinline__ void cp_wait0()  { asm volatile("cp.async.wait_group 0;"); }

template <bool ACCUM>
__global__ void __launch_bounds__(NTH, 1)
mca_attn_kernel(const float* __restrict__ Qg,   // [B, L, D] queries
                const float* __restrict__ KVg,  // [B, L, D] keys == values
                float* __restrict__ Og)         // [B, L, D]
{
    extern __shared__ float smem[];
    float* Qs  = smem;                 // BQ * ROWF
    float* KV0 = Qs  + BQ * ROWF;      // BK * ROWF
    float* KV1 = KV0 + BK * ROWF;      // BK * ROWF
    float* Ps  = KV1 + BK * ROWF;      // BQ * 33 (probabilities tile)

    const int tid = threadIdx.x;
    const int qt  = blockIdx.x;        // query tile 0..63
    const int b   = blockIdx.y;        // batch
    const int q   = tid >> 3;          // local query row 0..31
    const int s   = tid & 7;           // 8-way split: k-groups for S, d-slices for PV

    const float scale = 0.04419417382415922f;  // 1/sqrt(512)

    const float* qbase = Qg  + ((size_t)b * L_ + (size_t)qt * BQ) * D_;
    const float* kbase = KVg + (size_t)b * L_ * D_;

    // --- async load Q tile + KV tile 0 (32 rows x 128 float4 each; 16 per thread) ---
    #pragma unroll
    for (int i = 0; i < 16; ++i) {
        int f  = tid + i * NTH;        // float4 index 0..4095
        int r  = f >> 7;
        int c4 = f & 127;
        cp_async16(Qs + r * ROWF + c4 * 4, qbase + r * D_ + c4 * 4);
    }
    #pragma unroll
    for (int i = 0; i < 16; ++i) {
        int f  = tid + i * NTH;
        int r  = f >> 7;
        int c4 = f & 127;
        cp_async16(KV0 + r * ROWF + c4 * 4, kbase + r * D_ + c4 * 4);
    }
    cp_commit();

    // accumulator: this thread owns query row q, interleaved d-slices d4 = s + 8g
    float2 acc[32];
    #pragma unroll
    for (int j = 0; j < 32; ++j) acc[j] = make_float2(0.f, 0.f);
    float m = -INFINITY;
    float l = 0.f;

    cp_wait0();
    __syncthreads();

    for (int kt = 0; kt < NKT; ++kt) {
        float* cur = (kt & 1) ? KV1 : KV0;
        float* nxt = (kt & 1) ? KV0 : KV1;

        // prefetch next KV tile into the buffer we finished with last iteration
        if (kt + 1 < NKT) {
            const float* g = kbase + (size_t)(kt + 1) * BK * D_;
            #pragma unroll
            for (int i = 0; i < 16; ++i) {
                int f  = tid + i * NTH;
                int r  = f >> 7;
                int c4 = f & 127;
                cp_async16(nxt + r * ROWF + c4 * 4, g + r * D_ + c4 * 4);
            }
            cp_commit();
        }

        // ---- S = Q . K^T on this tile: thread computes S[q][s + 8c], c = 0..3 ----
        float2 sa0 = make_float2(0.f, 0.f), sa1 = sa0, sa2 = sa0, sa3 = sa0;
        const float4* qrow = reinterpret_cast<const float4*>(Qs + q * ROWF);
        const float4* k0   = reinterpret_cast<const float4*>(cur + (s +  0) * ROWF);
        const float4* k1   = reinterpret_cast<const float4*>(cur + (s +  8) * ROWF);
        const float4* k2   = reinterpret_cast<const float4*>(cur + (s + 16) * ROWF);
        const float4* k3   = reinterpret_cast<const float4*>(cur + (s + 24) * ROWF);
        #pragma unroll 4
        for (int dq = 0; dq < D_ / 4; ++dq) {
            float4 qv = qrow[dq];
            float2 ql = make_float2(qv.x, qv.y);
            float2 qh = make_float2(qv.z, qv.w);
            float4 kv;
            kv = k0[dq];
            sa0 = ffma2(ql, make_float2(kv.x, kv.y), sa0);
            sa0 = ffma2(qh, make_float2(kv.z, kv.w), sa0);
            kv = k1[dq];
            sa1 = ffma2(ql, make_float2(kv.x, kv.y), sa1);
            sa1 = ffma2(qh, make_float2(kv.z, kv.w), sa1);
            kv = k2[dq];
            sa2 = ffma2(ql, make_float2(kv.x, kv.y), sa2);
            sa2 = ffma2(qh, make_float2(kv.z, kv.w), sa2);
            kv = k3[dq];
            sa3 = ffma2(ql, make_float2(kv.x, kv.y), sa3);
            sa3 = ffma2(qh, make_float2(kv.z, kv.w), sa3);
        }
        float sv0 = (sa0.x + sa0.y) * scale;
        float sv1 = (sa1.x + sa1.y) * scale;
        float sv2 = (sa2.x + sa2.y) * scale;
        float sv3 = (sa3.x + sa3.y) * scale;

        // ---- online softmax over this tile's 32 keys (row group = 8 lanes) ----
        float mt = fmaxf(fmaxf(sv0, sv1), fmaxf(sv2, sv3));
        mt = fmaxf(mt, __shfl_xor_sync(0xffffffffu, mt, 1));
        mt = fmaxf(mt, __shfl_xor_sync(0xffffffffu, mt, 2));
        mt = fmaxf(mt, __shfl_xor_sync(0xffffffffu, mt, 4));
        float mnew = fmaxf(m, mt);
        float corr = __expf(m - mnew);           // exp(-inf)=0 on first tile
        float p0 = __expf(sv0 - mnew);
        float p1 = __expf(sv1 - mnew);
        float p2 = __expf(sv2 - mnew);
        float p3 = __expf(sv3 - mnew);
        float psum = p0 + p1 + p2 + p3;
        psum += __shfl_xor_sync(0xffffffffu, psum, 1);
        psum += __shfl_xor_sync(0xffffffffu, psum, 2);
        psum += __shfl_xor_sync(0xffffffffu, psum, 4);
        l = l * corr + psum;
        m = mnew;

        // share probabilities across the row group
        Ps[q * 33 + s +  0] = p0;
        Ps[q * 33 + s +  8] = p1;
        Ps[q * 33 + s + 16] = p2;
        Ps[q * 33 + s + 24] = p3;

        // rescale accumulator
        #pragma unroll
        for (int j = 0; j < 32; ++j) { acc[j].x *= corr; acc[j].y *= corr; }

        __syncthreads();   // Ps visible to whole block

        // ---- PV: acc[q, d-slice] += sum_k p[q][k] * V[k][d-slice] ----
        #pragma unroll 4
        for (int k = 0; k < BK; ++k) {
            float pv = Ps[q * 33 + k];
            float2 p2v = make_float2(pv, pv);
            const float4* vrow = reinterpret_cast<const float4*>(cur + k * ROWF) + s;
            #pragma unroll
            for (int g = 0; g < 16; ++g) {
                float4 v4 = vrow[8 * g];          // interleaved slices: conflict-free
                acc[2 * g]     = ffma2(p2v, make_float2(v4.x, v4.y), acc[2 * g]);
                acc[2 * g + 1] = ffma2(p2v, make_float2(v4.z, v4.w), acc[2 * g + 1]);
            }
        }

        cp_wait0();        // next tile's data landed (had a whole compute phase)
        __syncthreads();   // all reads of cur/Ps done before next prefetch/overwrite
    }

    // ---- epilogue: out = acc / l  (+ previous pass if ACCUM) ----
    float invl = 1.0f / l;
    float* orow = Og + ((size_t)b * L_ + (size_t)qt * BQ + q) * D_;
    #pragma unroll
    for (int g = 0; g < 16; ++g) {
        int d4 = s + 8 * g;                       // interleaved float4 slice
        float4 o;
        o.x = acc[2 * g].x     * invl;
        o.y = acc[2 * g].y     * invl;
        o.z = acc[2 * g + 1].x * invl;
        o.w = acc[2 * g + 1].y * invl;
        float4* optr = reinterpret_cast<float4*>(orow + d4 * 4);
        if (ACCUM) {
            float4 prev = *optr;
            o.x += prev.x; o.y += prev.y; o.z += prev.z; o.w += prev.w;
        }
        *optr = o;
    }
}

extern "C" void kernel_launch(void* const* d_in, const int* in_sizes, int n_in,
                              void* d_out, int out_size)
{
    (void)in_sizes; (void)n_in; (void)out_size;
    const float* x1 = (const float*)d_in[0];
    const float* x2 = (const float*)d_in[1];
    float* out = (float*)d_out;

    const size_t SMEM = (size_t)(BQ * ROWF + 2 * BK * ROWF + BQ * 33) * sizeof(float); // 202368 B
    cudaFuncSetAttribute(mca_attn_kernel<false>, cudaFuncAttributeMaxDynamicSharedMemorySize, (int)SMEM);
    cudaFuncSetAttribute(mca_attn_kernel<true>,  cudaFuncAttributeMaxDynamicSharedMemorySize, (int)SMEM);

    dim3 grid(L_ / BQ, B_);
    // pass 1: out  = softmax_k(x1 x2^T / sqrt(d)) x2
    mca_attn_kernel<false><<<grid, NTH, SMEM>>>(x1, x2, out);
    // pass 2: out += softmax_q(x2 x1^T / sqrt(d)) x1   (transpose-softmax branch)
    mca_attn_kernel<true ><<<grid, NTH, SMEM>>>(x2, x1, out);
}

// round 8
// speedup vs baseline: 1.0010x; 1.0000x over previous
#include <cuda_runtime.h>
#include <math.h>

// Mutual cross attention, B=8, L=2048, D=512, fp32.
// out = attn(x1, x2, x2) + attn(x2, x1, x1)   (flash-style, two passes)

#define B_   8
#define L_   2048
#define D_   512
#define BQ   32            // query rows per block
#define BK   32            // key rows per tile
#define PADF 4             // row padding in floats (row = 2064 B, shifts banks by 16B/row)
#define ROWF (D_ + PADF)   // 516 floats per smem row
#define NTH  256
#define NKT  (L_ / BK)     // 64 key tiles

// ---------- packed f32x2 FMA (Blackwell FFMA2) ----------
__device__ __forceinline__ float2 ffma2(float2 a, float2 b, float2 c) {
    float2 d;
    asm("{\n\t"
        ".reg .b64 ra, rb, rc, rd;\n\t"
        "mov.b64 ra, {%2, %3};\n\t"
        "mov.b64 rb, {%4, %5};\n\t"
        "mov.b64 rc, {%6, %7};\n\t"
        "fma.rn.f32x2 rd, ra, rb, rc;\n\t"
        "mov.b64 {%0, %1}, rd;\n\t"
        "}"
        : "=f"(d.x), "=f"(d.y)
        : "f"(a.x), "f"(a.y), "f"(b.x), "f"(b.y), "f"(c.x), "f"(c.y));
    return d;
}

// ---------- cp.async helpers ----------
__device__ __forceinline__ void cp_async16(float* smem_dst, const float* gmem_src) {
    unsigned saddr = (unsigned)__cvta_generic_to_shared(smem_dst);
    asm volatile("cp.async.cg.shared.global [%0], [%1], 16;" :: "r"(saddr), "l"(gmem_src));
}
__device__ __forceinline__ void cp_commit() { asm volatile("cp.async.commit_group;"); }
__device__ __forceinline__ void cp_wait0()  { asm volatile("cp.async.wait_group 0;"); }

template <bool ACCUM>
__global__ void __launch_bounds__(NTH, 1)
mca_attn_kernel(const float* __restrict__ Qg,   // [B, L, D] queries
                const float* __restrict__ KVg,  // [B, L, D] keys == values
                float* __restrict__ Og)         // [B, L, D]
{
    extern __shared__ float smem[];
    float* Qs  = smem;                 // BQ * ROWF
    float* KV0 = Qs  + BQ * ROWF;      // BK * ROWF
    float* KV1 = KV0 + BK * ROWF;      // BK * ROWF
    float* Ps  = KV1 + BK * ROWF;      // BQ * 33 (probabilities tile)

    const int tid = threadIdx.x;
    const int qt  = blockIdx.x;        // query tile 0..63
    const int b   = blockIdx.y;        // batch
    const int q   = tid >> 3;          // local query row 0..31
    const int s   = tid & 7;           // 8-way split: k-groups for S, d-slices for PV

    const float scale = 0.04419417382415922f;  // 1/sqrt(512)

    const float* qbase = Qg  + ((size_t)b * L_ + (size_t)qt * BQ) * D_;
    const float* kbase = KVg + (size_t)b * L_ * D_;

    // --- async load Q tile + KV tile 0 (32 rows x 128 float4 each; 16 per thread) ---
    #pragma unroll
    for (int i = 0; i < 16; ++i) {
        int f  = tid + i * NTH;        // float4 index 0..4095
        int r  = f >> 7;
        int c4 = f & 127;
        cp_async16(Qs + r * ROWF + c4 * 4, qbase + r * D_ + c4 * 4);
    }
    #pragma unroll
    for (int i = 0; i < 16; ++i) {
        int f  = tid + i * NTH;
        int r  = f >> 7;
        int c4 = f & 127;
        cp_async16(KV0 + r * ROWF + c4 * 4, kbase + r * D_ + c4 * 4);
    }
    cp_commit();

    // accumulator: this thread owns query row q, interleaved d-slices d4 = s + 8g
    float2 acc[32];
    #pragma unroll
    for (int j = 0; j < 32; ++j) acc[j] = make_float2(0.f, 0.f);
    float m = -INFINITY;
    float l = 0.f;

    cp_wait0();
    __syncthreads();

    for (int kt = 0; kt < NKT; ++kt) {
        float* cur = (kt & 1) ? KV1 : KV0;
        float* nxt = (kt & 1) ? KV0 : KV1;

        // prefetch next KV tile into the buffer we finished with last iteration
        if (kt + 1 < NKT) {
            const float* g = kbase + (size_t)(kt + 1) * BK * D_;
            #pragma unroll
            for (int i = 0; i < 16; ++i) {
                int f  = tid + i * NTH;
                int r  = f >> 7;
                int c4 = f & 127;
                cp_async16(nxt + r * ROWF + c4 * 4, g + r * D_ + c4 * 4);
            }
            cp_commit();
        }

        // ---- S = Q . K^T on this tile: thread computes S[q][s + 8c], c = 0..3 ----
        float2 sa0 = make_float2(0.f, 0.f), sa1 = sa0, sa2 = sa0, sa3 = sa0;
        const float4* qrow = reinterpret_cast<const float4*>(Qs + q * ROWF);
        const float4* k0   = reinterpret_cast<const float4*>(cur + (s +  0) * ROWF);
        const float4* k1   = reinterpret_cast<const float4*>(cur + (s +  8) * ROWF);
        const float4* k2   = reinterpret_cast<const float4*>(cur + (s + 16) * ROWF);
        const float4* k3   = reinterpret_cast<const float4*>(cur + (s + 24) * ROWF);
        #pragma unroll 4
        for (int dq = 0; dq < D_ / 4; ++dq) {
            float4 qv = qrow[dq];
            float2 ql = make_float2(qv.x, qv.y);
            float2 qh = make_float2(qv.z, qv.w);
            float4 kv;
            kv = k0[dq];
            sa0 = ffma2(ql, make_float2(kv.x, kv.y), sa0);
            sa0 = ffma2(qh, make_float2(kv.z, kv.w), sa0);
            kv = k1[dq];
            sa1 = ffma2(ql, make_float2(kv.x, kv.y), sa1);
            sa1 = ffma2(qh, make_float2(kv.z, kv.w), sa1);
            kv = k2[dq];
            sa2 = ffma2(ql, make_float2(kv.x, kv.y), sa2);
            sa2 = ffma2(qh, make_float2(kv.z, kv.w), sa2);
            kv = k3[dq];
            sa3 = ffma2(ql, make_float2(kv.x, kv.y), sa3);
            sa3 = ffma2(qh, make_float2(kv.z, kv.w), sa3);
        }
        float sv0 = (sa0.x + sa0.y) * scale;
        float sv1 = (sa1.x + sa1.y) * scale;
        float sv2 = (sa2.x + sa2.y) * scale;
        float sv3 = (sa3.x + sa3.y) * scale;

        // ---- online softmax over this tile's 32 keys (row group = 8 lanes) ----
        float mt = fmaxf(fmaxf(sv0, sv1), fmaxf(sv2, sv3));
        mt = fmaxf(mt, __shfl_xor_sync(0xffffffffu, mt, 1));
        mt = fmaxf(mt, __shfl_xor_sync(0xffffffffu, mt, 2));
        mt = fmaxf(mt, __shfl_xor_sync(0xffffffffu, mt, 4));
        float mnew = fmaxf(m, mt);
        float corr = __expf(m - mnew);           // exp(-inf)=0 on first tile
        float p0 = __expf(sv0 - mnew);
        float p1 = __expf(sv1 - mnew);
        float p2 = __expf(sv2 - mnew);
        float p3 = __expf(sv3 - mnew);
        float psum = p0 + p1 + p2 + p3;
        psum += __shfl_xor_sync(0xffffffffu, psum, 1);
        psum += __shfl_xor_sync(0xffffffffu, psum, 2);
        psum += __shfl_xor_sync(0xffffffffu, psum, 4);
        l = l * corr + psum;
        m = mnew;

        // share probabilities across the row group
        Ps[q * 33 + s +  0] = p0;
        Ps[q * 33 + s +  8] = p1;
        Ps[q * 33 + s + 16] = p2;
        Ps[q * 33 + s + 24] = p3;

        // rescale accumulator
        #pragma unroll
        for (int j = 0; j < 32; ++j) { acc[j].x *= corr; acc[j].y *= corr; }

        __syncthreads();   // Ps visible to whole block

        // ---- PV: acc[q, d-slice] += sum_k p[q][k] * V[k][d-slice] ----
        #pragma unroll 4
        for (int k = 0; k < BK; ++k) {
            float pv = Ps[q * 33 + k];
            float2 p2v = make_float2(pv, pv);
            const float4* vrow = reinterpret_cast<const float4*>(cur + k * ROWF) + s;
            #pragma unroll
            for (int g = 0; g < 16; ++g) {
                float4 v4 = vrow[8 * g];          // interleaved slices: conflict-free
                acc[2 * g]     = ffma2(p2v, make_float2(v4.x, v4.y), acc[2 * g]);
                acc[2 * g + 1] = ffma2(p2v, make_float2(v4.z, v4.w), acc[2 * g + 1]);
            }
        }

        cp_wait0();        // next tile's data landed (had a whole compute phase)
        __syncthreads();   // all reads of cur/Ps done before next prefetch/overwrite
    }

    // ---- epilogue: out = acc / l  (+ previous pass if ACCUM) ----
    float invl = 1.0f / l;
    float* orow = Og + ((size_t)b * L_ + (size_t)qt * BQ + q) * D_;
    #pragma unroll
    for (int g = 0; g < 16; ++g) {
        int d4 = s + 8 * g;                       // interleaved float4 slice
        float4 o;
        o.x = acc[2 * g].x     * invl;
        o.y = acc[2 * g].y     * invl;
        o.z = acc[2 * g + 1].x * invl;
        o.w = acc[2 * g + 1].y * invl;
        float4* optr = reinterpret_cast<float4*>(orow + d4 * 4);
        if (ACCUM) {
            float4 prev = *optr;
            o.x += prev.x; o.y += prev.y; o.z += prev.z; o.w += prev.w;
        }
        *optr = o;
    }
}

extern "C" void kernel_launch(void* const* d_in, const int* in_sizes, int n_in,
                              void* d_out, int out_size)
{
    (void)in_sizes; (void)n_in; (void)out_size;
    const float* x1 = (const float*)d_in[0];
    const float* x2 = (const float*)d_in[1];
    float* out = (float*)d_out;

    const size_t SMEM = (size_t)(BQ * ROWF + 2 * BK * ROWF + BQ * 33) * sizeof(float); // 202368 B
    cudaFuncSetAttribute(mca_attn_kernel<false>, cudaFuncAttributeMaxDynamicSharedMemorySize, (int)SMEM);
    cudaFuncSetAttribute(mca_attn_kernel<true>,  cudaFuncAttributeMaxDynamicSharedMemorySize, (int)SMEM);

    dim3 grid(L_ / BQ, B_);
    // pass 1: out  = softmax_k(x1 x2^T / sqrt(d)) x2
    mca_attn_kernel<false><<<grid, NTH, SMEM>>>(x1, x2, out);
    // pass 2: out += softmax_q(x2 x1^T / sqrt(d)) x1   (transpose-softmax branch)
    mca_attn_kernel<true ><<<grid, NTH, SMEM>>>(x2, x1, out);
}